// round 2
// baseline (speedup 1.0000x reference)
#include <cuda_runtime.h>
#include <cstdint>
#include <math.h>

// GCNEncoder: B=4, N=512, D=128, L=3. Complete graph + extra self loop:
// deg == 513 for every node -> norm == 1/513 on every edge, so
//   GCNConv(h) = (colsum(h@W) + h@W)/513 + b   (per graph)
// Entire network = 3 fp32 GEMMs [2048,128]x[128,128] + colsums + epilogues.
// Latency-class problem -> ONE persistent kernel, software grid barriers.

#define NODES 512
#define BATCH 4
#define DIM   128
#define RTOT  (NODES * BATCH)        // 2048
#define TM    32
#define TN    64
#define BPG   (NODES / TM)           // 16 row-tiles per graph
#define BND   (BATCH * NODES * DIM)  // 262144
#define NBLK  128u                   // grid size (all co-resident)

__device__ __constant__ float c_inv = 1.0f / 513.0f;

// Scratch (device globals; allocations are forbidden)
__device__ float g_H0[RTOT * DIM];
__device__ float g_GA[RTOT * DIM];
__device__ float g_GB[RTOT * DIM];
__device__ float g_SPA[BATCH * BPG * DIM];
__device__ float g_SPB[BATCH * BPG * DIM];
__device__ unsigned g_bar[3];        // zeroed via cudaMemsetAsync each launch

typedef unsigned long long ull;

__device__ __forceinline__ ull fma2(ull a, ull b, ull c) {
    ull d;
    asm("fma.rn.f32x2 %0, %1, %2, %3;" : "=l"(d) : "l"(a), "l"(b), "l"(c));
    return d;
}
__device__ __forceinline__ ull pack2(float h) {
    unsigned int u = __float_as_uint(h);
    ull d;
    asm("mov.b64 %0, {%1, %1};" : "=l"(d) : "r"(u));
    return d;
}
__device__ __forceinline__ void unpack2(ull v, float& lo, float& hi) {
    unsigned int a, b;
    asm("mov.b64 {%0, %1}, %2;" : "=r"(a), "=r"(b) : "l"(v));
    lo = __uint_as_float(a);
    hi = __uint_as_float(b);
}

// ---- grid barrier (split arrive/wait; counters memset to 0 per launch) ----
__device__ __forceinline__ void bar_arrive(int i) {
    __syncthreads();                       // all warps done with pre-barrier smem/global
    if (threadIdx.x == 0) {
        __threadfence();                   // publish our global stores
        atomicAdd(&g_bar[i], 1u);
    }
}
__device__ __forceinline__ void bar_wait(int i) {
    if (threadIdx.x == 0) {
        while (atomicAdd(&g_bar[i], 0u) < NBLK) { }
        __threadfence();
    }
    __syncthreads();
}

// ---- GEMM core: sH[32][128] (XOR-swizzled) x sW[128][64] -> 32x64 tile ----
// Writes G tile + deterministic per-block column partial sums. Reuses sH as
// reduction scratch (caller must rebuild sH afterwards).
__device__ __forceinline__ void gemm_store(float* sH, const float* sW,
                                           int row0, int c0,
                                           float* __restrict__ Gout,
                                           float* __restrict__ SPout,
                                           int tid) {
    const int ty = tid >> 3;
    const int tx = tid & 7;
    const int cA = tx * 4;
    const int cB = tx * 4 + 32;
    const int swz = (ty & 7) << 2;

    ull acc0 = 0, acc1 = 0, acc2 = 0, acc3 = 0;

    #pragma unroll 8
    for (int k = 0; k < DIM; k++) {
        ull hp = pack2(sH[ty * DIM + (k ^ swz)]);
        ulonglong2 wa = *(const ulonglong2*)&sW[k * TN + cA];
        ulonglong2 wb = *(const ulonglong2*)&sW[k * TN + cB];
        acc0 = fma2(hp, wa.x, acc0);
        acc1 = fma2(hp, wa.y, acc1);
        acc2 = fma2(hp, wb.x, acc2);
        acc3 = fma2(hp, wb.y, acc3);
    }

    float oA0, oA1, oA2, oA3, oB0, oB1, oB2, oB3;
    unpack2(acc0, oA0, oA1);
    unpack2(acc1, oA2, oA3);
    unpack2(acc2, oB0, oB1);
    unpack2(acc3, oB2, oB3);

    const int rg = row0 + ty;
    *(float4*)&Gout[rg * DIM + c0 + cA] = make_float4(oA0, oA1, oA2, oA3);
    *(float4*)&Gout[rg * DIM + c0 + cB] = make_float4(oB0, oB1, oB2, oB3);

    __syncthreads();
    float* sRed = sH;  // reuse as [32][64]
    *(float4*)&sRed[ty * TN + cA] = make_float4(oA0, oA1, oA2, oA3);
    *(float4*)&sRed[ty * TN + cB] = make_float4(oB0, oB1, oB2, oB3);
    __syncthreads();

    if (tid < TN) {
        float s = 0.0f;
        #pragma unroll
        for (int r = 0; r < TM; r++) s += sRed[r * TN + tid];
        const int g  = row0 >> 9;
        const int rt = (row0 & 511) >> 5;
        SPout[(g * BPG + rt) * DIM + c0 + tid] = s;
    }
}

__device__ __forceinline__ void load_w(float* sW, const float* __restrict__ W,
                                       int c0, int tid) {
    const int kr = tid >> 4;
    const int cq = (tid & 15) * 4;
    #pragma unroll
    for (int i = 0; i < 8; i++) {
        const int k = kr + i * 16;
        *(float4*)&sW[k * TN + cq] = *(const float4*)&W[k * DIM + c0 + cq];
    }
}

// Epilogue: h = relu((S + G)/513 + b) into swizzled sH.  All cross-barrier
// global reads use __ldcg (L1 may hold stale lines within this launch).
__device__ __forceinline__ void epi(const float* __restrict__ Gin,
                                    const float* __restrict__ SPi,
                                    const float* __restrict__ bvec,
                                    float* sH, int row0, int g, int tid) {
    const int d  = tid & 127;
    const int rh = tid >> 7;
    float s = 0.0f;
    #pragma unroll
    for (int p = 0; p < BPG; p++) s += __ldcg(&SPi[(g * BPG + p) * DIM + d]);
    const float bd = bvec[d];
    #pragma unroll
    for (int j = 0; j < 16; j++) {
        const int r  = j * 2 + rh;
        const int rg = row0 + r;
        const float v = __ldcg(&Gin[rg * DIM + d]);
        sH[r * DIM + (d ^ ((r & 7) << 2))] = fmaxf((s + v) * c_inv + bd, 0.0f);
    }
}

__global__ void __launch_bounds__(256) k_fused(const float* __restrict__ x,
                                               const float* __restrict__ W0,
                                               const float* __restrict__ b0,
                                               const float* __restrict__ Ws,
                                               const float* __restrict__ bs,
                                               float* __restrict__ out,
                                               int write_nf) {
    __shared__ __align__(16) float sW[DIM * TN];
    __shared__ __align__(16) float sH[TM * DIM];
    const int tid  = threadIdx.x;
    const int bx   = blockIdx.x;
    const int row0 = (bx >> 1) * TM;
    const int c0   = (bx & 1) * TN;
    const int g    = row0 >> 9;

    // ---- stage 0: h0 = x@W0+b0 (store node_feature), GEMM0 -> GA/SPA ----
    load_w(sW, Ws, c0, tid);
    {
        const int d  = tid & 127;
        const int rh = tid >> 7;
        const float w0d = W0[d], w1d = W0[DIM + d], bd = b0[d];
        #pragma unroll
        for (int j = 0; j < 16; j++) {
            const int r  = j * 2 + rh;
            const int rg = row0 + r;
            const float h = x[rg * 2] * w0d + x[rg * 2 + 1] * w1d + bd;
            sH[r * DIM + (d ^ ((r & 7) << 2))] = h;
            if (c0 == 0) g_H0[rg * DIM + d] = h;
        }
    }
    __syncthreads();
    gemm_store(sH, sW, row0, c0, g_GA, g_SPA, tid);

    bar_arrive(0);
    load_w(sW, Ws + DIM * DIM, c0, tid);     // hide W1 load in the barrier gap
    bar_wait(0);

    // ---- stage 1: relu epilogue(GA,SPA,bs0) -> GEMM1 -> GB/SPB ----
    epi(g_GA, g_SPA, bs, sH, row0, g, tid);
    __syncthreads();
    gemm_store(sH, sW, row0, c0, g_GB, g_SPB, tid);

    bar_arrive(1);
    load_w(sW, Ws + 2 * DIM * DIM, c0, tid); // hide W2 load
    bar_wait(1);

    // ---- stage 2: relu epilogue(GB,SPB,bs1) -> GEMM2 -> GA/SPA ----
    epi(g_GB, g_SPB, bs + DIM, sH, row0, g, tid);
    __syncthreads();
    gemm_store(sH, sW, row0, c0, g_GA, g_SPA, tid);

    bar_arrive(2);
    bar_wait(2);

    // ---- stage 3: z=(S+GA)/513+bs2; out = log_softmax(z) + h0 (+ emit h0) ----
    {
        const int r0f = bx * 16;             // 16 rows per block, within one graph
        const int g2  = r0f >> 9;
        float* sS = sH;                      // reuse smem
        if (tid < DIM) {
            float s = 0.0f;
            #pragma unroll
            for (int p = 0; p < BPG; p++)
                s += __ldcg(&g_SPA[(g2 * BPG + p) * DIM + tid]);
            sS[tid] = s;
        }
        __syncthreads();

        const int w    = tid >> 5;
        const int lane = tid & 31;
        const int d0 = lane, d1 = lane + 32, d2 = lane + 64, d3 = lane + 96;
        const float bz0 = bs[2 * DIM + d0], bz1 = bs[2 * DIM + d1];
        const float bz2 = bs[2 * DIM + d2], bz3 = bs[2 * DIM + d3];

        #pragma unroll
        for (int rr = 0; rr < 2; rr++) {
            const int r = r0f + w * 2 + rr;
            const float* G = &g_GA[r * DIM];
            float z0 = (sS[d0] + __ldcg(&G[d0])) * c_inv + bz0;
            float z1 = (sS[d1] + __ldcg(&G[d1])) * c_inv + bz1;
            float z2 = (sS[d2] + __ldcg(&G[d2])) * c_inv + bz2;
            float z3 = (sS[d3] + __ldcg(&G[d3])) * c_inv + bz3;

            float m = fmaxf(fmaxf(z0, z1), fmaxf(z2, z3));
            #pragma unroll
            for (int o = 16; o > 0; o >>= 1)
                m = fmaxf(m, __shfl_xor_sync(0xFFFFFFFFu, m, o));
            float e = expf(z0 - m) + expf(z1 - m) + expf(z2 - m) + expf(z3 - m);
            #pragma unroll
            for (int o = 16; o > 0; o >>= 1)
                e += __shfl_xor_sync(0xFFFFFFFFu, e, o);
            const float lse = m + logf(e);

            const float* H = &g_H0[r * DIM];
            const float h0 = __ldcg(&H[d0]), h1 = __ldcg(&H[d1]);
            const float h2 = __ldcg(&H[d2]), h3 = __ldcg(&H[d3]);
            float* O = &out[r * DIM];
            O[d0] = z0 - lse + h0;
            O[d1] = z1 - lse + h1;
            O[d2] = z2 - lse + h2;
            O[d3] = z3 - lse + h3;
            if (write_nf) {
                float* O2 = &out[BND + r * DIM];
                O2[d0] = h0; O2[d1] = h1; O2[d2] = h2; O2[d3] = h3;
            }
        }
    }
}

extern "C" void kernel_launch(void* const* d_in, const int* in_sizes, int n_in,
                              void* d_out, int out_size) {
    const float* x  = (const float*)d_in[0];  // [4,512,2]
    const float* W0 = (const float*)d_in[1];  // [2,128]
    const float* b0 = (const float*)d_in[2];  // [128]
    const float* Ws = (const float*)d_in[3];  // [3,128,128]
    const float* bs = (const float*)d_in[4];  // [3,128]
    // d_in[5] = edge_index: analytically redundant (complete graph + self loops)
    float* out = (float*)d_out;
    const int write_nf = (out_size >= 2 * BND) ? 1 : 0;

    void* bar_ptr = nullptr;
    cudaGetSymbolAddress(&bar_ptr, g_bar);
    cudaMemsetAsync(bar_ptr, 0, 3 * sizeof(unsigned), 0);

    k_fused<<<NBLK, 256>>>(x, W0, b0, Ws, bs, out, write_nf);
}

// round 3
// speedup vs baseline: 1.0103x; 1.0103x over previous
#include <cuda_runtime.h>
#include <cstdint>
#include <math.h>

// GCNEncoder: B=4, N=512, D=128, L=3. Complete graph + extra self loop ->
// deg==513 everywhere, norm==1/513 on every edge:
//   GCNConv(h) = (colsum(h@W) + h@W)/513 + b        (per graph)
// One persistent kernel, 256 blocks (2/SM), software grid barriers.
// GEMM layout: lane=row (32 rows), warp=4-col group (8 warps -> 32 cols).
//   W read is warp-broadcast (16B/wavefront), H read is 32-consecutive-rows
//   from a transposed, XOR-swizzled sHT (128B/wavefront). 1.125 B/FMA.

#define NODES 512
#define BATCH 4
#define DIM   128
#define RTOT  2048
#define TM    32
#define TC    32
#define BPG   16                      // row-tiles per graph
#define BND   262144
#define NBLK  256u

__device__ float g_H0[RTOT * DIM];
__device__ float g_GA[RTOT * DIM];
__device__ float g_GB[RTOT * DIM];
__device__ float g_SPA[BATCH * BPG * DIM];
__device__ float g_SPB[BATCH * BPG * DIM];
__device__ unsigned g_bar[3];         // memset to 0 per launch

__device__ __constant__ float c_inv = 1.0f / 513.0f;

typedef unsigned long long ull;

__device__ __forceinline__ ull fma2(ull a, ull b, ull c) {
    ull d;
    asm("fma.rn.f32x2 %0, %1, %2, %3;" : "=l"(d) : "l"(a), "l"(b), "l"(c));
    return d;
}
__device__ __forceinline__ ull add2(ull a, ull b) {
    ull d;
    asm("add.rn.f32x2 %0, %1, %2;" : "=l"(d) : "l"(a), "l"(b));
    return d;
}
__device__ __forceinline__ ull pack2(float h) {
    unsigned int u = __float_as_uint(h);
    ull d;
    asm("mov.b64 %0, {%1, %1};" : "=l"(d) : "r"(u));
    return d;
}
__device__ __forceinline__ void unpack2(ull v, float& lo, float& hi) {
    unsigned int a, b;
    asm("mov.b64 {%0, %1}, %2;" : "=r"(a), "=r"(b) : "l"(v));
    lo = __uint_as_float(a);
    hi = __uint_as_float(b);
}

// ---- grid barrier: atomic arrive, volatile-load spin with backoff ----
__device__ __forceinline__ void bar_arrive(int i, int tid) {
    __syncthreads();
    if (tid == 0) {
        __threadfence();
        atomicAdd(&g_bar[i], 1u);
    }
}
__device__ __forceinline__ void bar_wait(int i, int tid) {
    if (tid == 0) {
        volatile unsigned* p = &g_bar[i];
        while (*p < NBLK) __nanosleep(64);
        __threadfence();
    }
    __syncthreads();
}

// ---- W tile load: sW[k][32] = Ws_layer[k][c0..c0+31] ----
__device__ __forceinline__ void load_w(float* sW, const float* __restrict__ W,
                                       int c0, int tid) {
    const int k = tid >> 1;           // 2 threads per k-row
    const int h = (tid & 1) * 16;
    #pragma unroll
    for (int j = 0; j < 4; j++)
        *(float4*)&sW[k * TC + h + j * 4] =
            *(const float4*)&W[k * DIM + c0 + h + j * 4];
}

// ---- GEMM core: out[32 rows][32 cols] from sHT[k][row] x sW[k][col] ----
// Also produces per-block column partial sums via lane butterfly (no smem).
__device__ __forceinline__ void gemm32(const float* sHT, const float* sW,
                                       int row0, int c0, int g, int rtg,
                                       float* __restrict__ Gout,
                                       float* __restrict__ SPout,
                                       int w, int l) {
    ull a0 = 0, a1 = 0;
    const float* wp = sW + w * 4;

    #pragma unroll
    for (int kb = 0; kb < 32; kb++) {
        const int ls = l ^ (kb & 7);          // S(k)=(k>>2)&7, const per kb
        #pragma unroll
        for (int q = 0; q < 4; q++) {
            const int k = kb * 4 + q;
            ull hp = pack2(sHT[k * TC + ls]);
            ulonglong2 wv = *(const ulonglong2*)(wp + k * TC);  // broadcast
            a0 = fma2(hp, wv.x, a0);
            a1 = fma2(hp, wv.y, a1);
        }
    }

    float o0, o1, o2, o3;
    unpack2(a0, o0, o1);
    unpack2(a1, o2, o3);
    *(float4*)&Gout[(row0 + l) * DIM + c0 + w * 4] = make_float4(o0, o1, o2, o3);

    // column sums over the 32 rows (lanes) via butterfly
    ull s0 = a0, s1 = a1;
    #pragma unroll
    for (int o = 16; o > 0; o >>= 1) {
        s0 = add2(s0, __shfl_xor_sync(0xFFFFFFFFu, s0, o));
        s1 = add2(s1, __shfl_xor_sync(0xFFFFFFFFu, s1, o));
    }
    if (l == 0) {
        float p0, p1, p2, p3;
        unpack2(s0, p0, p1);
        unpack2(s1, p2, p3);
        *(float4*)&SPout[(g * BPG + rtg) * DIM + c0 + w * 4] =
            make_float4(p0, p1, p2, p3);
    }
}

// ---- layer epilogue: h = relu((S + G)/513 + b), transposed into sHT ----
// thread: rl = tid>>3 (row), m = tid&7; covers d = 4*(m+8j)+q, j<4, q<4.
// sHT index: d*32 + (row ^ ((d>>2)&7)); here (d>>2)&7 == m (const per thread).
__device__ __forceinline__ void epi(const float* __restrict__ Gin,
                                    const float* __restrict__ SP,
                                    const float* __restrict__ bvec,
                                    float* sHT, float* sS,
                                    int row0, int g, int tid) {
    const int rl = tid >> 3;
    const int m  = tid & 7;
    const int rg = row0 + rl;

    // prefetch G (coalesced 128B per same-row octet)
    float4 gv[4];
    #pragma unroll
    for (int j = 0; j < 4; j++)
        gv[j] = __ldg((const float4*)&Gin[rg * DIM + 4 * (m + 8 * j)]);
    // NOTE: Gin/SP written pre-barrier by other SMs; must bypass stale L1.
    // __ldg caches in L1 — replace with __ldcg loads:
    #pragma unroll
    for (int j = 0; j < 4; j++) {
        const float* p = &Gin[rg * DIM + 4 * (m + 8 * j)];
        gv[j].x = __ldcg(p + 0);
        gv[j].y = __ldcg(p + 1);
        gv[j].z = __ldcg(p + 2);
        gv[j].w = __ldcg(p + 3);
    }

    if (tid < DIM) {
        float s = 0.0f;
        #pragma unroll
        for (int p = 0; p < BPG; p++)
            s += __ldcg(&SP[(g * BPG + p) * DIM + tid]);
        sS[tid] = s;
    }
    __syncthreads();

    #pragma unroll
    for (int j = 0; j < 4; j++) {
        const int d0 = 4 * (m + 8 * j);
        const float* fv = (const float*)&gv[j];
        #pragma unroll
        for (int q = 0; q < 4; q++) {
            const int d = d0 + q;
            const float h = fmaxf((sS[d] + fv[q]) * c_inv + __ldg(&bvec[d]), 0.0f);
            sHT[d * TC + (rl ^ m)] = h;
        }
    }
}

__global__ void __launch_bounds__(256) k_fused(const float* __restrict__ x,
                                               const float* __restrict__ W0,
                                               const float* __restrict__ b0,
                                               const float* __restrict__ Ws,
                                               const float* __restrict__ bs,
                                               float* __restrict__ out,
                                               int write_nf) {
    __shared__ __align__(16) float sW[DIM * TC];    // 16 KB
    __shared__ __align__(16) float sHT[DIM * TC];   // 16 KB (k-major, swizzled)
    __shared__ float sS[DIM];

    const int tid  = threadIdx.x;
    const int bx   = blockIdx.x;
    const int w    = tid >> 5;
    const int l    = tid & 31;
    const int rt   = bx >> 2;            // global row-tile 0..63
    const int ct   = bx & 3;             // col-tile 0..3
    const int row0 = rt * TM;
    const int c0   = ct * TC;
    const int g    = rt >> 4;
    const int rtg  = rt & 15;

    // ---- stage 0: h0 = x@W0 + b0 -> sHT (+ g_H0), GEMM0 -> GA/SPA ----
    load_w(sW, Ws, c0, tid);
    {
        const int rl = tid >> 3;
        const int m  = tid & 7;
        const int rg = row0 + rl;
        const float x0 = x[rg * 2], x1 = x[rg * 2 + 1];
        #pragma unroll
        for (int j = 0; j < 4; j++) {
            const int d0 = 4 * (m + 8 * j);
            float4 hv;
            float* hp = (float*)&hv;
            #pragma unroll
            for (int q = 0; q < 4; q++) {
                const int d = d0 + q;
                const float h = x0 * __ldg(&W0[d]) + x1 * __ldg(&W0[DIM + d])
                                + __ldg(&b0[d]);
                hp[q] = h;
                sHT[d * TC + (rl ^ m)] = h;
            }
            if (ct == 0) *(float4*)&g_H0[rg * DIM + d0] = hv;
        }
    }
    __syncthreads();
    gemm32(sHT, sW, row0, c0, g, rtg, g_GA, g_SPA, w, l);

    bar_arrive(0, tid);
    load_w(sW, Ws + DIM * DIM, c0, tid);      // overlap W1 load with barrier
    bar_wait(0, tid);

    // ---- stage 1 ----
    epi(g_GA, g_SPA, bs, sHT, sS, row0, g, tid);
    __syncthreads();
    gemm32(sHT, sW, row0, c0, g, rtg, g_GB, g_SPB, w, l);

    bar_arrive(1, tid);
    load_w(sW, Ws + 2 * DIM * DIM, c0, tid);  // overlap W2 load
    bar_wait(1, tid);

    // ---- stage 2 ----
    epi(g_GB, g_SPB, bs + DIM, sHT, sS, row0, g, tid);
    __syncthreads();
    gemm32(sHT, sW, row0, c0, g, rtg, g_GA, g_SPA, w, l);

    bar_arrive(2, tid);
    bar_wait(2, tid);

    // ---- stage 3: out = log_softmax((S+GA)/513 + bs2) + h0 (+ emit h0) ----
    {
        const int r0f = bx * 8;               // 8 rows per block
        const int g2  = r0f >> 9;
        if (tid < DIM) {
            float s = 0.0f;
            #pragma unroll
            for (int p = 0; p < BPG; p++)
                s += __ldcg(&g_SPA[(g2 * BPG + p) * DIM + tid]);
            sS[tid] = s;
        }
        __syncthreads();

        const int r  = r0f + w;               // warp per row
        const int d0 = l, d1 = l + 32, d2 = l + 64, d3 = l + 96;
        const float* G = &g_GA[r * DIM];
        float z0 = (sS[d0] + __ldcg(&G[d0])) * c_inv + __ldg(&bs[2 * DIM + d0]);
        float z1 = (sS[d1] + __ldcg(&G[d1])) * c_inv + __ldg(&bs[2 * DIM + d1]);
        float z2 = (sS[d2] + __ldcg(&G[d2])) * c_inv + __ldg(&bs[2 * DIM + d2]);
        float z3 = (sS[d3] + __ldcg(&G[d3])) * c_inv + __ldg(&bs[2 * DIM + d3]);

        float mx = fmaxf(fmaxf(z0, z1), fmaxf(z2, z3));
        #pragma unroll
        for (int o = 16; o > 0; o >>= 1)
            mx = fmaxf(mx, __shfl_xor_sync(0xFFFFFFFFu, mx, o));
        float e = __expf(z0 - mx) + __expf(z1 - mx) +
                  __expf(z2 - mx) + __expf(z3 - mx);
        #pragma unroll
        for (int o = 16; o > 0; o >>= 1)
            e += __shfl_xor_sync(0xFFFFFFFFu, e, o);
        const float lse = mx + __logf(e);

        const float* H = &g_H0[r * DIM];
        const float h0 = __ldcg(&H[d0]), h1 = __ldcg(&H[d1]);
        const float h2 = __ldcg(&H[d2]), h3 = __ldcg(&H[d3]);
        float* O = &out[r * DIM];
        O[d0] = z0 - lse + h0;
        O[d1] = z1 - lse + h1;
        O[d2] = z2 - lse + h2;
        O[d3] = z3 - lse + h3;
        if (write_nf) {
            float* O2 = &out[BND + r * DIM];
            O2[d0] = h0; O2[d1] = h1; O2[d2] = h2; O2[d3] = h3;
        }
    }
}

extern "C" void kernel_launch(void* const* d_in, const int* in_sizes, int n_in,
                              void* d_out, int out_size) {
    const float* x  = (const float*)d_in[0];  // [4,512,2]
    const float* W0 = (const float*)d_in[1];  // [2,128]
    const float* b0 = (const float*)d_in[2];  // [128]
    const float* Ws = (const float*)d_in[3];  // [3,128,128]
    const float* bs = (const float*)d_in[4];  // [3,128]
    // d_in[5] = edge_index: redundant (complete graph + self loops)
    float* out = (float*)d_out;
    const int write_nf = (out_size >= 2 * BND) ? 1 : 0;

    void* bar_ptr = nullptr;
    cudaGetSymbolAddress(&bar_ptr, g_bar);
    cudaMemsetAsync(bar_ptr, 0, 3 * sizeof(unsigned), 0);

    k_fused<<<NBLK, 256>>>(x, W0, b0, Ws, bs, out, write_nf);
}

// round 4
// speedup vs baseline: 1.3842x; 1.3701x over previous
#include <cuda_runtime.h>
#include <cstdint>
#include <math.h>

// GCNEncoder B=4,N=512,D=128,L=3. Complete graph + extra self loop:
//   deg==513 -> GCNConv(h) = (colsum(h@W) + h@W)/513 + b   (per graph)
// NEW: h0 = [x|1]A is rank-3 -> layer-1 GEMM collapses analytically:
//   h1 = relu((x0*p0 + x1*p1)/513... see stage1; P = A@W1 [3x128].
// Only 2 real GEMMs (h1@W2, h2@W3). One persistent kernel, 2 grid barriers.
// GEMM: 256 blocks x 128 thr; block tile 32x32; thread 2 rows x 4 cols;
// per k: LDS.64(h) + LDS.128(W broadcast-free) + 4 FFMA2 -> fma-bound.

#define DIM   128
#define NODES 512
#define BATCH 4
#define RTOT  2048
#define TM    32
#define TN    32
#define BPG   16                    // 32-row tiles per graph
#define BND   262144
#define NBLK  256u
#define THR   128

__device__ float g_GA[RTOT * DIM];
__device__ float g_GB[RTOT * DIM];
__device__ float g_SPA[BATCH * BPG * DIM];
__device__ float g_SPB[BATCH * BPG * DIM];
__device__ unsigned g_bar[64];      // counters at [0] and [32] (pad lines)

#define C_INV (1.0f / 513.0f)

typedef unsigned long long ull;

__device__ __forceinline__ ull fma2(ull a, ull b, ull c) {
    ull d;
    asm("fma.rn.f32x2 %0, %1, %2, %3;" : "=l"(d) : "l"(a), "l"(b), "l"(c));
    return d;
}
__device__ __forceinline__ ull add2(ull a, ull b) {
    ull d;
    asm("add.rn.f32x2 %0, %1, %2;" : "=l"(d) : "l"(a), "l"(b));
    return d;
}
__device__ __forceinline__ ull pack2(float h) {
    unsigned u = __float_as_uint(h);
    ull d;
    asm("mov.b64 %0, {%1, %1};" : "=l"(d) : "r"(u));
    return d;
}
__device__ __forceinline__ void unpack2(ull v, float& lo, float& hi) {
    unsigned a, b;
    asm("mov.b64 {%0, %1}, %2;" : "=r"(a), "=r"(b) : "l"(v));
    lo = __uint_as_float(a);
    hi = __uint_as_float(b);
}

__device__ __forceinline__ void bar_arrive(int i, int tid) {
    __syncthreads();
    if (tid == 0) {
        __threadfence();
        atomicAdd(&g_bar[i * 32], 1u);
    }
}
__device__ __forceinline__ void bar_wait(int i, int tid) {
    if (tid == 0) {
        volatile unsigned* p = &g_bar[i * 32];
        while (*p < NBLK) __nanosleep(32);
        __threadfence();
    }
    __syncthreads();
}

// sW[k][32 cols] <- W[k][c0..c0+31], 128B rows, coalesced.
__device__ __forceinline__ void load_w(float* sW, const float* __restrict__ W,
                                       int c0, int tid) {
    const int tx = tid & 7, k0 = tid >> 3;
    #pragma unroll
    for (int i = 0; i < 8; i++) {
        const int k = k0 + i * 16;
        *(float4*)&sW[k * TN + tx * 4] = *(const float4*)&W[k * DIM + c0 + tx * 4];
    }
}

// GEMM: sHT[k][32 rows (16B-chunk swizzled)] x sW[k][32 cols] -> 32x32 tile.
// Thread (ty=tid>>3 in 0..15, tx=tid&7): rows 2ty,2ty+1; cols 4tx..4tx+3.
__device__ __forceinline__ void gemm(const float* sHT, const float* sW,
                                     float* sRed, int row0, int c0,
                                     int g, int rtg,
                                     float* __restrict__ Gout,
                                     float* __restrict__ SPout, int tid) {
    const int tx = tid & 7, ty = tid >> 3;
    const int hc = ty >> 1;             // chunk of row pair
    const int hoff = (ty & 1) << 1;     // float offset within chunk
    const float* wp = sW + tx * 4;

    ull a00 = 0, a01 = 0, a10 = 0, a11 = 0;
    #pragma unroll 2
    for (int kb = 0; kb < DIM; kb += 8) {
        #pragma unroll
        for (int j = 0; j < 8; j++) {
            const int k = kb + j;
            float2 h2 = *(const float2*)&sHT[k * TM + ((hc ^ j) << 2) + hoff];
            ulonglong2 wv = *(const ulonglong2*)(wp + k * TN);
            ull h0 = pack2(h2.x), h1 = pack2(h2.y);
            a00 = fma2(h0, wv.x, a00);
            a01 = fma2(h0, wv.y, a01);
            a10 = fma2(h1, wv.x, a10);
            a11 = fma2(h1, wv.y, a11);
        }
    }

    float o0, o1, o2, o3;
    const int rg = row0 + ty * 2;
    unpack2(a00, o0, o1); unpack2(a01, o2, o3);
    *(float4*)&Gout[rg * DIM + c0 + tx * 4] = make_float4(o0, o1, o2, o3);
    unpack2(a10, o0, o1); unpack2(a11, o2, o3);
    *(float4*)&Gout[(rg + 1) * DIM + c0 + tx * 4] = make_float4(o0, o1, o2, o3);

    // column partial sums over the 32 rows (deterministic order)
    ull s0 = add2(a00, a10), s1 = add2(a01, a11);
    s0 = add2(s0, __shfl_xor_sync(0xFFFFFFFFu, s0, 8));
    s0 = add2(s0, __shfl_xor_sync(0xFFFFFFFFu, s0, 16));
    s1 = add2(s1, __shfl_xor_sync(0xFFFFFFFFu, s1, 8));
    s1 = add2(s1, __shfl_xor_sync(0xFFFFFFFFu, s1, 16));
    __syncthreads();
    if ((tid & 31) < 8) {
        const int w = tid >> 5;
        float p0, p1, p2, p3;
        unpack2(s0, p0, p1); unpack2(s1, p2, p3);
        *(float4*)&sRed[w * TN + tx * 4] = make_float4(p0, p1, p2, p3);
    }
    __syncthreads();
    if (tid < TN) {
        float s = sRed[tid] + sRed[TN + tid] + sRed[2 * TN + tid] + sRed[3 * TN + tid];
        SPout[(g * BPG + rtg) * DIM + c0 + tid] = s;
    }
}

// h = relu((S + G)/513 + b) -> sHT (thread owns one d = k-row of sHT).
__device__ __forceinline__ void epi(const float* __restrict__ Gin,
                                    const float* __restrict__ SP,
                                    const float* __restrict__ bvec,
                                    float* sHT, int row0, int g, int tid) {
    const int d = tid;
    float S = 0.f;
    #pragma unroll
    for (int p = 0; p < BPG; p++) S += __ldcg(&SP[(g * BPG + p) * DIM + d]);
    const float bd = __ldg(&bvec[d]);
    const int swz = d & 7;

    #pragma unroll
    for (int half = 0; half < 2; half++) {
        const int rb = half * 16;
        float v[16];
        #pragma unroll
        for (int i = 0; i < 16; i++)
            v[i] = __ldcg(&Gin[(row0 + rb + i) * DIM + d]);  // MLP 16
        #pragma unroll
        for (int cb = 0; cb < 4; cb++) {
            float4 hv;
            hv.x = fmaxf((S + v[cb * 4 + 0]) * C_INV + bd, 0.f);
            hv.y = fmaxf((S + v[cb * 4 + 1]) * C_INV + bd, 0.f);
            hv.z = fmaxf((S + v[cb * 4 + 2]) * C_INV + bd, 0.f);
            hv.w = fmaxf((S + v[cb * 4 + 3]) * C_INV + bd, 0.f);
            const int chunk = (half * 4 + cb) ^ swz;
            *(float4*)&sHT[d * TM + (chunk << 2)] = hv;
        }
    }
}

__global__ void __launch_bounds__(THR) k_fused(const float* __restrict__ x,
                                               const float* __restrict__ W0,
                                               const float* __restrict__ b0,
                                               const float* __restrict__ Ws,
                                               const float* __restrict__ bs,
                                               float* __restrict__ out,
                                               int write_nf) {
    __shared__ __align__(16) float sW[DIM * TN];    // 16 KB
    __shared__ __align__(16) float sHT[DIM * TM];   // 16 KB
    __shared__ __align__(16) float sS[DIM];         // doubles as sRed
    __shared__ float sA[3 * DIM];                   // [W0 row0; W0 row1; b0]
    __shared__ float sX[TM * 2];
    __shared__ float sB[8];

    const int tid  = threadIdx.x;
    const int bx   = blockIdx.x;
    const int rt   = bx >> 2;            // 0..63
    const int ct   = bx & 3;
    const int row0 = rt * TM;
    const int c0   = ct * TN;
    const int g    = rt >> 4;
    const int rtg  = rt & 15;
    const int d    = tid;                // 0..127

    // ---- prologue: sA, sX, graph sum s_g, sW=W2 ----
    sA[d]           = __ldg(&W0[d]);
    sA[DIM + d]     = __ldg(&W0[DIM + d]);
    sA[2 * DIM + d] = __ldg(&b0[d]);
    if (tid < TM) *(float2*)&sX[tid * 2] = *(const float2*)&x[(row0 + tid) * 2];
    load_w(sW, Ws + DIM * DIM, c0, tid);            // W2 for gemmA

    {
        const float* xg = x + g * NODES * 2;
        float sx0 = 0.f, sx1 = 0.f;
        #pragma unroll
        for (int i = 0; i < 4; i++) {
            float2 t = *(const float2*)&xg[(tid + i * 128) * 2];
            sx0 += t.x; sx1 += t.y;
        }
        #pragma unroll
        for (int o = 16; o > 0; o >>= 1) {
            sx0 += __shfl_xor_sync(0xFFFFFFFFu, sx0, o);
            sx1 += __shfl_xor_sync(0xFFFFFFFFu, sx1, o);
        }
        if ((tid & 31) == 0) {
            sB[(tid >> 5) * 2]     = sx0;
            sB[(tid >> 5) * 2 + 1] = sx1;
        }
    }
    __syncthreads();
    const float sg0 = sB[0] + sB[2] + sB[4] + sB[6];
    const float sg1 = sB[1] + sB[3] + sB[5] + sB[7];

    // ---- P[:,d] = A @ W1 column d  (W1 = Ws[0]) ----
    float p0 = 0.f, p1 = 0.f, p2 = 0.f;
    {
        const float* __restrict__ W1 = Ws;
        #pragma unroll 8
        for (int k = 0; k < DIM; k++) {
            const float wv = __ldg(&W1[k * DIM + d]);
            p0 += sA[k] * wv;
            p1 += sA[DIM + k] * wv;
            p2 += sA[2 * DIM + k] * wv;
        }
    }

    // ---- stage 1: h1 = relu(x0*q0 + x1*q1 + u) -> sHT  (layer-1 collapsed) ----
    {
        const float q0 = p0 * C_INV, q1 = p1 * C_INV;
        const float u  = (sg0 * p0 + sg1 * p1) * C_INV + p2 + __ldg(&bs[d]);
        const int swz = d & 7;
        #pragma unroll
        for (int cb = 0; cb < 8; cb++) {
            float4 hv;
            float* hp = (float*)&hv;
            #pragma unroll
            for (int i = 0; i < 4; i++) {
                const int r = cb * 4 + i;
                hp[i] = fmaxf(sX[r * 2] * q0 + sX[r * 2 + 1] * q1 + u, 0.f);
            }
            *(float4*)&sHT[d * TM + ((cb ^ swz) << 2)] = hv;
        }
    }
    __syncthreads();

    // ---- gemmA: h1 @ W2 -> GA, SPA ----
    gemm(sHT, sW, sS, row0, c0, g, rtg, g_GA, g_SPA, tid);

    bar_arrive(0, tid);
    load_w(sW, Ws + 2 * DIM * DIM, c0, tid);        // W3, hidden in barrier gap
    bar_wait(0, tid);

    // ---- stage 2: h2 = relu((GA+SA)/513 + b2) -> sHT; gemmB -> GB, SPB ----
    epi(g_GA, g_SPA, bs + DIM, sHT, row0, g, tid);
    __syncthreads();
    gemm(sHT, sW, sS, row0, c0, g, rtg, g_GB, g_SPB, tid);

    bar_arrive(1, tid);
    bar_wait(1, tid);

    // ---- final: z=(GB+SB)/513+b3; out = log_softmax(z) + h0 (+ emit h0) ----
    {
        const int r0f = bx * 8;              // 8 rows per block
        const int g2  = r0f >> 9;
        float s = 0.f;
        #pragma unroll
        for (int p = 0; p < BPG; p++)
            s += __ldcg(&g_SPB[(g2 * BPG + p) * DIM + tid]);
        sS[tid] = s;
        __syncthreads();

        const int w = tid >> 5, l = tid & 31;
        #pragma unroll
        for (int rr = 0; rr < 2; rr++) {
            const int r = r0f + w * 2 + rr;
            const float x0 = __ldg(&x[r * 2]), x1 = __ldg(&x[r * 2 + 1]);
            float z[4], h0v[4];
            #pragma unroll
            for (int q = 0; q < 4; q++) {
                const int dd = l + q * 32;
                z[q] = (sS[dd] + __ldcg(&g_GB[r * DIM + dd])) * C_INV
                       + __ldg(&bs[2 * DIM + dd]);
                h0v[q] = x0 * sA[dd] + x1 * sA[DIM + dd] + sA[2 * DIM + dd];
            }
            float mx = fmaxf(fmaxf(z[0], z[1]), fmaxf(z[2], z[3]));
            #pragma unroll
            for (int o = 16; o > 0; o >>= 1)
                mx = fmaxf(mx, __shfl_xor_sync(0xFFFFFFFFu, mx, o));
            float e = __expf(z[0] - mx) + __expf(z[1] - mx) +
                      __expf(z[2] - mx) + __expf(z[3] - mx);
            #pragma unroll
            for (int o = 16; o > 0; o >>= 1)
                e += __shfl_xor_sync(0xFFFFFFFFu, e, o);
            const float lse = mx + __logf(e);

            #pragma unroll
            for (int q = 0; q < 4; q++) {
                const int dd = l + q * 32;
                out[r * DIM + dd] = z[q] - lse + h0v[q];
                if (write_nf) out[BND + r * DIM + dd] = h0v[q];
            }
        }
    }
}

extern "C" void kernel_launch(void* const* d_in, const int* in_sizes, int n_in,
                              void* d_out, int out_size) {
    const float* x  = (const float*)d_in[0];  // [4,512,2]
    const float* W0 = (const float*)d_in[1];  // [2,128]
    const float* b0 = (const float*)d_in[2];  // [128]
    const float* Ws = (const float*)d_in[3];  // [3,128,128]
    const float* bs = (const float*)d_in[4];  // [3,128]
    // d_in[5] = edge_index: redundant (complete graph + self loops)
    float* out = (float*)d_out;
    const int write_nf = (out_size >= 2 * BND) ? 1 : 0;

    void* bar_ptr = nullptr;
    cudaGetSymbolAddress(&bar_ptr, g_bar);
    cudaMemsetAsync(bar_ptr, 0, 64 * sizeof(unsigned), 0);

    k_fused<<<NBLK, THR>>>(x, W0, b0, Ws, bs, out, write_nf);
}